// round 16
// baseline (speedup 1.0000x reference)
#include <cuda_runtime.h>
#include <cuda_fp16.h>
#include <cstdint>
#include <cstddef>

// ============================================================================
// WaveletBasis: out[B,O] = haar_basis(x).coeffs + x @ base_weight ; kl = 0
//   B=32768, F=1024, O=64, NB=8
// One fp16 GEMM (fp32 accum) on mma.sync HMMA:
//   out = A[B,8192] * Bm[8192,64] + bias
// Per feature f (8 K-slots), j = clip(floor(8u),0,7), u=(tanh x+1)/2:
//   A slots = [x, s0, s1, s0s1, s2, s1s2, s0s2, s0s1s2]  (signs from bits of j)
//   Bm rows = [bw, c1, R(c2+c3), R(c2-c3), H4-rotated c4..c7 / 2], R=sqrt2/2
//   bias[o] = sum_f coeffs[f,o,0]
// j computed WITHOUT tanh: u >= i/8  <=>  x >= atanh(i/4 - 1).
//
// History: R11 K-split4 129.9us (main ~= legacy-HMMA floor ~113us).
//   R12 fp16-acc regressed; R14 1-barrier ring regressed; R15 LUT neutral.
//   => main is AT the tensor floor; remaining cost is auxiliary kernels.
// R16: fuse the reduce INTO wb_main's epilogue via per-tile arrival counter
//   (last split-CTA sums partials 0..3 in fixed order + bias -> out; resets
//   counter for graph replay). Removes the 9us reduce kernel + 32MB DRAM read.
// ============================================================================

static constexpr int FDIM = 1024;
static constexpr int NCHUNK = 128;           // K chunks of 64 (8 features)
static constexpr int NSPLIT = 4;
static constexpr int CH_PER = NCHUNK / NSPLIT;   // 32 chunks per CTA
static constexpr int NTILES = 256;
static constexpr int OUT_ELEMS = 32768 * 64;

#define T1 (-0.9729550745276566f)
#define T2 (-0.5493061443340548f)
#define T3 (-0.2554128118829953f)
#define T5 ( 0.2554128118829953f)
#define T6 ( 0.5493061443340548f)
#define T7 ( 0.9729550745276566f)

// B operand fp16, linear chunk layout: [kt=128][n=64][kp=8] uint4 = 1 MB
__device__ uint4 g_B4[NCHUNK * 512];
__device__ float g_bias[64];
// K-split partial sums: [split][B*O] fp32 = 32 MB scratch
__device__ float g_part[NSPLIT * OUT_ELEMS];
// per-tile arrival counters (zero-init; reset by reducer each launch)
__device__ int g_done[NTILES];

// ---------------------------------------------------------------------------
// Prologue 1: rotated B matrix (fp16), float4-vectorized loads
// ---------------------------------------------------------------------------
__global__ void wb_prep_B(const float* __restrict__ coeffs,
                          const float* __restrict__ bw) {
    int gid = blockIdx.x * blockDim.x + threadIdx.x;   // 65536 = F*O
    int f = gid >> 6;
    int o = gid & 63;
    const float4* c4 = (const float4*)(coeffs + (size_t)gid * 8);
    float4 lo = c4[0], hi = c4[1];
    float c1 = lo.y, c2 = lo.z, c3 = lo.w;
    float c4v = hi.x, c5 = hi.y, c6 = hi.z, c7 = hi.w;
    float wv = bw[gid];
    const float R = 0.70710678118654752f;
    float v[8];
    v[0] = wv;
    v[1] = c1;
    v[2] = R * (c2 + c3);
    v[3] = R * (c2 - c3);
    v[4] = 0.5f * (c4v + c5 + c6 + c7);
    v[5] = 0.5f * (c4v - c5 + c6 - c7);
    v[6] = 0.5f * (c4v + c5 - c6 - c7);
    v[7] = 0.5f * (c4v - c5 - c6 + c7);
    unsigned p[4];
#pragma unroll
    for (int i = 0; i < 4; i++) {
        unsigned plo = (unsigned)__half_as_ushort(__float2half(v[2 * i]));
        unsigned phi = (unsigned)__half_as_ushort(__float2half(v[2 * i + 1]));
        p[i] = plo | (phi << 16);
    }
    uint4 pk; pk.x = p[0]; pk.y = p[1]; pk.z = p[2]; pk.w = p[3];
    int kt = f >> 3, fl = f & 7;
    g_B4[kt * 512 + o * 8 + fl] = pk;
}

// ---------------------------------------------------------------------------
// Prologue 2: bias[o] = sum_f coeffs[f,o,0]; also zero the kl tail of out
// ---------------------------------------------------------------------------
__global__ void wb_prep_bias(const float* __restrict__ coeffs,
                             float* __restrict__ out, int out_size) {
    __shared__ float red[128];
    int o = blockIdx.x;
    int t = threadIdx.x;
    float s = 0.f;
    for (int f = t; f < FDIM; f += 128)
        s += coeffs[(size_t)(f * 64 + o) * 8];
    red[t] = s;
    __syncthreads();
#pragma unroll
    for (int st = 64; st > 0; st >>= 1) {
        if (t < st) red[t] += red[t + st];
        __syncthreads();
    }
    if (t == 0) {
        g_bias[o] = red[0];
        if (o == 0) {
            for (int k = OUT_ELEMS; k < out_size; k++) out[k] = 0.f;
        }
    }
}

// ---------------------------------------------------------------------------
// Main GEMM: 1024 CTAs x 128 threads. CTA = (tile, split). R11-verified
// fragment maps. Epilogue: write partial; last split-CTA per tile reduces.
// ---------------------------------------------------------------------------
#define LDMX4(R, ADDR)                                                        \
    asm volatile("ldmatrix.sync.aligned.m8n8.x4.shared.b16 {%0,%1,%2,%3}, [%4];" \
                 : "=r"((R)[0]), "=r"((R)[1]), "=r"((R)[2]), "=r"((R)[3])     \
                 : "r"(ADDR))
#define MMA16816(C, A, B0, B1)                                                \
    asm volatile("mma.sync.aligned.m16n8k16.row.col.f32.f16.f16.f32 "         \
                 "{%0,%1,%2,%3}, {%4,%5,%6,%7}, {%8,%9}, {%0,%1,%2,%3};"      \
                 : "+f"((C)[0]), "+f"((C)[1]), "+f"((C)[2]), "+f"((C)[3])     \
                 : "r"((A)[0]), "r"((A)[1]), "r"((A)[2]), "r"((A)[3]),        \
                   "r"(B0), "r"(B1))

__global__ void __launch_bounds__(128, 4)
wb_main(const float* __restrict__ x, float* __restrict__ out) {
    __shared__ __half As[128][72];   // padded 144 B stride: conflict-free
    __shared__ __half Bs[64][72];

    const int t = threadIdx.x;
    const int w = t >> 5;
    const int l = t & 31;
    const int tile  = blockIdx.x & 255;
    const int split = blockIdx.x >> 8;
    const int kt0 = split * CH_PER;

    float acc[2][8][4];
#pragma unroll
    for (int g = 0; g < 2; g++)
#pragma unroll
        for (int nb = 0; nb < 8; nb++)
#pragma unroll
            for (int i = 0; i < 4; i++) acc[g][nb][i] = 0.f;

    // A fragment addresses (verified R4/R11 mapping)
    uint32_t a_addr0 = (uint32_t)__cvta_generic_to_shared(
        &As[w * 32 + (l & 15)][(l >> 4) * 8]);
    uint32_t a_addr1 = (uint32_t)__cvta_generic_to_shared(
        &As[w * 32 + 16 + (l & 15)][(l >> 4) * 8]);
    // B fragment addresses via x4 n-pairs (verified R7/R11 mapping)
    const uint32_t bs_base = (uint32_t)__cvta_generic_to_shared(&Bs[0][0]);
    uint32_t b_off[4];
#pragma unroll
    for (int p = 0; p < 4; p++)
        b_off[p] = bs_base + (uint32_t)((p * 16 + ((l >> 4) << 3) + (l & 7)) * 144 +
                                        ((l >> 3) & 1) * 16);

    for (int ki = 0; ki < CH_PER; ki++) {
        const int kt = kt0 + ki;
        __syncthreads();  // previous compute done before overwriting tiles

        // ---- generate A chunk: rows 0..127, 8 features ----
#pragma unroll
        for (int j = 0; j < 2; j++) {
            int id = t + j * 128;
            int row = id >> 1, half = id & 1;
            const float4 xv = *(const float4*)(
                x + (size_t)(tile * 128 + row) * FDIM + kt * 8 + half * 4);
            float xa[4] = {xv.x, xv.y, xv.z, xv.w};
#pragma unroll
            for (int i = 0; i < 4; i++) {
                float xs = xa[i];
                bool b2 = xs >= 0.0f;
                bool b1 = xs >= (b2 ? T6 : T2);
                bool b0 = xs >= (b2 ? (b1 ? T7 : T5) : (b1 ? T3 : T1));
                unsigned s0 = b2 ? 0x8000u : 0u;
                unsigned s1 = b1 ? 0x8000u : 0u;
                unsigned s2 = b0 ? 0x8000u : 0u;
                const unsigned ONE = 0x3C00u;
                unsigned hx = (unsigned)__half_as_ushort(__float2half(xs));
                uint4 pk;
                pk.x = hx | ((ONE | s0) << 16);
                pk.y = (ONE | s1) | ((ONE | (s0 ^ s1)) << 16);
                pk.z = (ONE | s2) | ((ONE | (s1 ^ s2)) << 16);
                pk.w = (ONE | (s0 ^ s2)) | ((ONE | (s0 ^ s1 ^ s2)) << 16);
                *(uint4*)&As[row][(half * 4 + i) * 8] = pk;
            }
        }

        // ---- copy B chunk: 512 uint4 ----
#pragma unroll
        for (int j = 0; j < 4; j++) {
            int id = t + j * 128;
            int n = id >> 3, kp = id & 7;
            *(uint4*)&Bs[n][kp * 8] = g_B4[(kt * 64 + n) * 8 + kp];
        }

        __syncthreads();

        // ---- compute: 4 k16 steps ----
#pragma unroll
        for (int ks = 0; ks < 4; ks++) {
            const uint32_t koff = (uint32_t)(ks * 32);
            uint32_t a0[4], a1[4], bf[4][4];
            LDMX4(a0, a_addr0 + koff);
            LDMX4(a1, a_addr1 + koff);
#pragma unroll
            for (int p = 0; p < 4; p++) LDMX4(bf[p], b_off[p] + koff);
#pragma unroll
            for (int p = 0; p < 4; p++) {
                MMA16816(acc[0][2 * p],     a0, bf[p][0], bf[p][1]);
                MMA16816(acc[1][2 * p],     a1, bf[p][0], bf[p][1]);
                MMA16816(acc[0][2 * p + 1], a0, bf[p][2], bf[p][3]);
                MMA16816(acc[1][2 * p + 1], a1, bf[p][2], bf[p][3]);
            }
        }
    }

    // ---- epilogue: write fp32 partial ----
    float* part = g_part + (size_t)split * OUT_ELEMS;
    const int col0 = (l & 3) * 2;
#pragma unroll
    for (int g = 0; g < 2; g++) {
        int row0 = tile * 128 + w * 32 + g * 16 + (l >> 2);
#pragma unroll
        for (int nb = 0; nb < 8; nb++) {
            float2 v0, v1;
            v0.x = acc[g][nb][0];
            v0.y = acc[g][nb][1];
            v1.x = acc[g][nb][2];
            v1.y = acc[g][nb][3];
            *(float2*)(part + (size_t)row0 * 64 + nb * 8 + col0) = v0;
            *(float2*)(part + (size_t)(row0 + 8) * 64 + nb * 8 + col0) = v1;
        }
    }

    // ---- arrival protocol: last split-CTA for this tile reduces ----
    __threadfence();                 // make this CTA's partial visible
    __syncthreads();                 // all threads' stores + fences done
    __shared__ int s_last;
    if (t == 0)
        s_last = (atomicAdd(&g_done[tile], 1) == NSPLIT - 1) ? 1 : 0;
    __syncthreads();
    if (!s_last) return;
    __threadfence();                 // acquire: other CTAs' partials visible

    // ---- fused reduce: fixed order p0+p1 + p2+p3 + bias (deterministic) ----
    float2 bias2[8];
#pragma unroll
    for (int nb = 0; nb < 8; nb++)
        bias2[nb] = *(const float2*)&g_bias[nb * 8 + col0];

#pragma unroll
    for (int g = 0; g < 2; g++) {
        int row0 = tile * 128 + w * 32 + g * 16 + (l >> 2);
#pragma unroll
        for (int nb = 0; nb < 8; nb++) {
#pragma unroll
            for (int rr = 0; rr < 2; rr++) {
                size_t idx = (size_t)(row0 + rr * 8) * 64 + nb * 8 + col0;
                float2 p0 = *(const float2*)(g_part + idx);
                float2 p1 = *(const float2*)(g_part + idx + (size_t)OUT_ELEMS);
                float2 p2 = *(const float2*)(g_part + idx + 2 * (size_t)OUT_ELEMS);
                float2 p3 = *(const float2*)(g_part + idx + 3 * (size_t)OUT_ELEMS);
                float2 r;
                r.x = (p0.x + p1.x) + (p2.x + p3.x) + bias2[nb].x;
                r.y = (p0.y + p1.y) + (p2.y + p3.y) + bias2[nb].y;
                *(float2*)(out + idx) = r;
            }
        }
    }

    if (t == 0) g_done[tile] = 0;    // reset for next graph replay
}

// ---------------------------------------------------------------------------
extern "C" void kernel_launch(void* const* d_in, const int* in_sizes, int n_in,
                              void* d_out, int out_size) {
    const float* x      = (const float*)d_in[0];   // [32768,1024] f32
    const float* coeffs = (const float*)d_in[1];   // [1024,64,8]  f32
    const float* bw     = (const float*)d_in[2];   // [1024,64]    f32
    float* out = (float*)d_out;

    wb_prep_B<<<512, 128>>>(coeffs, bw);
    wb_prep_bias<<<64, 128>>>(coeffs, out, out_size);
    wb_main<<<NTILES * NSPLIT, 128>>>(x, out);
}

// round 17
// speedup vs baseline: 1.0814x; 1.0814x over previous
#include <cuda_runtime.h>
#include <cuda_fp16.h>
#include <cstdint>
#include <cstddef>

// ============================================================================
// WaveletBasis: out[B,O] = haar_basis(x).coeffs + x @ base_weight ; kl = 0
//   B=32768, F=1024, O=64, NB=8
// One fp16 GEMM (fp32 accum) on mma.sync HMMA:
//   out = A[B,8192] * Bm[8192,64] + bias
// Per feature f (8 K-slots), j = clip(floor(8u),0,7), u=(tanh x+1)/2:
//   A slots = [x, s0, s1, s0s1, s2, s1s2, s0s2, s0s1s2]  (signs from bits of j)
//   Bm rows = [bw, c1, R(c2+c3), R(c2-c3), H4-rotated c4..c7 / 2], R=sqrt2/2
//   bias[o] = sum_f coeffs[f,o,0]
// j computed WITHOUT tanh: u >= i/8  <=>  x >= atanh(i/4 - 1).
//
// History: R11 K-split4 129.9us; main ~= legacy-HMMA floor (~114us) —
//   confirmed by R12 (+instr regressed), R15 (-instr neutral), R16 (fused
//   reduce regressed). R17: keep R11 main byte-exact; store K-split partials
//   as HALF2 (traffic 32->16MB) and shrink the reduce kernel (~9.1 -> ~4.5us).
//   Error budget: +5e-4 RSS -> ~5.5e-4 total, under the 1e-3 gate.
// ============================================================================

static constexpr int FDIM = 1024;
static constexpr int NCHUNK = 128;           // K chunks of 64 (8 features)
static constexpr int NSPLIT = 4;
static constexpr int CH_PER = NCHUNK / NSPLIT;   // 32 chunks per CTA
static constexpr int OUT_ELEMS = 32768 * 64;

#define T1 (-0.9729550745276566f)
#define T2 (-0.5493061443340548f)
#define T3 (-0.2554128118829953f)
#define T5 ( 0.2554128118829953f)
#define T6 ( 0.5493061443340548f)
#define T7 ( 0.9729550745276566f)

// B operand fp16, linear chunk layout: [kt=128][n=64][kp=8] uint4 = 1 MB
__device__ uint4 g_B4[NCHUNK * 512];
__device__ float g_bias[64];
// K-split partial sums, HALF2-packed: [split][B*O/2] = 16 MB scratch
__device__ unsigned g_parth[NSPLIT * OUT_ELEMS / 2];

// ---------------------------------------------------------------------------
// Prologue 1: rotated B matrix (fp16)  (R11-measured: 5.1us)
// ---------------------------------------------------------------------------
__global__ void wb_prep_B(const float* __restrict__ coeffs,
                          const float* __restrict__ bw) {
    int gid = blockIdx.x * blockDim.x + threadIdx.x;   // 65536 = F*O
    int f = gid >> 6;
    int o = gid & 63;
    const float* c = coeffs + (size_t)(f * 64 + o) * 8;
    float c1 = c[1], c2 = c[2], c3 = c[3];
    float c4 = c[4], c5 = c[5], c6 = c[6], c7 = c[7];
    float w = bw[f * 64 + o];
    const float R = 0.70710678118654752f;
    float v[8];
    v[0] = w;
    v[1] = c1;
    v[2] = R * (c2 + c3);
    v[3] = R * (c2 - c3);
    v[4] = 0.5f * (c4 + c5 + c6 + c7);
    v[5] = 0.5f * (c4 - c5 + c6 - c7);
    v[6] = 0.5f * (c4 + c5 - c6 - c7);
    v[7] = 0.5f * (c4 - c5 - c6 + c7);
    unsigned p[4];
#pragma unroll
    for (int i = 0; i < 4; i++) {
        unsigned lo = (unsigned)__half_as_ushort(__float2half(v[2 * i]));
        unsigned hi = (unsigned)__half_as_ushort(__float2half(v[2 * i + 1]));
        p[i] = lo | (hi << 16);
    }
    uint4 pk; pk.x = p[0]; pk.y = p[1]; pk.z = p[2]; pk.w = p[3];
    int kt = f >> 3, fl = f & 7;
    g_B4[kt * 512 + o * 8 + fl] = pk;
}

// ---------------------------------------------------------------------------
// Prologue 2: bias[o] = sum_f coeffs[f,o,0]   (deterministic tree reduce)
// ---------------------------------------------------------------------------
__global__ void wb_prep_bias(const float* __restrict__ coeffs) {
    __shared__ float red[128];
    int o = blockIdx.x;
    int t = threadIdx.x;
    float s = 0.f;
    for (int f = t; f < FDIM; f += 128)
        s += coeffs[(size_t)(f * 64 + o) * 8];
    red[t] = s;
    __syncthreads();
#pragma unroll
    for (int st = 64; st > 0; st >>= 1) {
        if (t < st) red[t] += red[t + st];
        __syncthreads();
    }
    if (t == 0) g_bias[o] = red[0];
}

// ---------------------------------------------------------------------------
// Main GEMM: 1024 CTAs x 128 threads. CTA = (tile, split). R11 main loop
// byte-exact; epilogue stores half2 partials.
// ---------------------------------------------------------------------------
#define LDMX4(R, ADDR)                                                        \
    asm volatile("ldmatrix.sync.aligned.m8n8.x4.shared.b16 {%0,%1,%2,%3}, [%4];" \
                 : "=r"((R)[0]), "=r"((R)[1]), "=r"((R)[2]), "=r"((R)[3])     \
                 : "r"(ADDR))
#define MMA16816(C, A, B0, B1)                                                \
    asm volatile("mma.sync.aligned.m16n8k16.row.col.f32.f16.f16.f32 "         \
                 "{%0,%1,%2,%3}, {%4,%5,%6,%7}, {%8,%9}, {%0,%1,%2,%3};"      \
                 : "+f"((C)[0]), "+f"((C)[1]), "+f"((C)[2]), "+f"((C)[3])     \
                 : "r"((A)[0]), "r"((A)[1]), "r"((A)[2]), "r"((A)[3]),        \
                   "r"(B0), "r"(B1))

__global__ void __launch_bounds__(128, 4)
wb_main(const float* __restrict__ x) {
    __shared__ __half As[128][72];   // padded 144 B stride: conflict-free
    __shared__ __half Bs[64][72];

    const int t = threadIdx.x;
    const int w = t >> 5;
    const int l = t & 31;
    const int tile  = blockIdx.x & 255;
    const int split = blockIdx.x >> 8;
    const int kt0 = split * CH_PER;

    float acc[2][8][4];
#pragma unroll
    for (int g = 0; g < 2; g++)
#pragma unroll
        for (int nb = 0; nb < 8; nb++)
#pragma unroll
            for (int i = 0; i < 4; i++) acc[g][nb][i] = 0.f;

    // A fragment addresses (verified R4/R11 mapping)
    uint32_t a_addr0 = (uint32_t)__cvta_generic_to_shared(
        &As[w * 32 + (l & 15)][(l >> 4) * 8]);
    uint32_t a_addr1 = (uint32_t)__cvta_generic_to_shared(
        &As[w * 32 + 16 + (l & 15)][(l >> 4) * 8]);
    // B fragment addresses via x4 n-pairs (verified R7/R11 mapping)
    const uint32_t bs_base = (uint32_t)__cvta_generic_to_shared(&Bs[0][0]);
    uint32_t b_off[4];
#pragma unroll
    for (int p = 0; p < 4; p++)
        b_off[p] = bs_base + (uint32_t)((p * 16 + ((l >> 4) << 3) + (l & 7)) * 144 +
                                        ((l >> 3) & 1) * 16);

    for (int ki = 0; ki < CH_PER; ki++) {
        const int kt = kt0 + ki;
        __syncthreads();  // previous compute done before overwriting tiles

        // ---- generate A chunk: rows 0..127, 8 features ----
#pragma unroll
        for (int j = 0; j < 2; j++) {
            int id = t + j * 128;
            int row = id >> 1, half = id & 1;
            const float4 xv = *(const float4*)(
                x + (size_t)(tile * 128 + row) * FDIM + kt * 8 + half * 4);
            float xa[4] = {xv.x, xv.y, xv.z, xv.w};
#pragma unroll
            for (int i = 0; i < 4; i++) {
                float xs = xa[i];
                bool b2 = xs >= 0.0f;
                bool b1 = xs >= (b2 ? T6 : T2);
                bool b0 = xs >= (b2 ? (b1 ? T7 : T5) : (b1 ? T3 : T1));
                unsigned s0 = b2 ? 0x8000u : 0u;
                unsigned s1 = b1 ? 0x8000u : 0u;
                unsigned s2 = b0 ? 0x8000u : 0u;
                const unsigned ONE = 0x3C00u;
                unsigned hx = (unsigned)__half_as_ushort(__float2half(xs));
                uint4 pk;
                pk.x = hx | ((ONE | s0) << 16);
                pk.y = (ONE | s1) | ((ONE | (s0 ^ s1)) << 16);
                pk.z = (ONE | s2) | ((ONE | (s1 ^ s2)) << 16);
                pk.w = (ONE | (s0 ^ s2)) | ((ONE | (s0 ^ s1 ^ s2)) << 16);
                *(uint4*)&As[row][(half * 4 + i) * 8] = pk;
            }
        }

        // ---- copy B chunk: 512 uint4 ----
#pragma unroll
        for (int j = 0; j < 4; j++) {
            int id = t + j * 128;
            int n = id >> 3, kp = id & 7;
            *(uint4*)&Bs[n][kp * 8] = g_B4[(kt * 64 + n) * 8 + kp];
        }

        __syncthreads();

        // ---- compute: 4 k16 steps ----
#pragma unroll
        for (int ks = 0; ks < 4; ks++) {
            const uint32_t koff = (uint32_t)(ks * 32);
            uint32_t a0[4], a1[4], bf[4][4];
            LDMX4(a0, a_addr0 + koff);
            LDMX4(a1, a_addr1 + koff);
#pragma unroll
            for (int p = 0; p < 4; p++) LDMX4(bf[p], b_off[p] + koff);
#pragma unroll
            for (int p = 0; p < 4; p++) {
                MMA16816(acc[0][2 * p],     a0, bf[p][0], bf[p][1]);
                MMA16816(acc[1][2 * p],     a1, bf[p][0], bf[p][1]);
                MMA16816(acc[0][2 * p + 1], a0, bf[p][2], bf[p][3]);
                MMA16816(acc[1][2 * p + 1], a1, bf[p][2], bf[p][3]);
            }
        }
    }

    // ---- epilogue: store HALF2 partials (bias added in reduce) ----
    unsigned* parth = g_parth + (size_t)split * (OUT_ELEMS / 2);
    const int col0 = (l & 3) * 2;
#pragma unroll
    for (int g = 0; g < 2; g++) {
        int row0 = tile * 128 + w * 32 + g * 16 + (l >> 2);
#pragma unroll
        for (int nb = 0; nb < 8; nb++) {
            size_t idx0 = (size_t)row0 * 64 + nb * 8 + col0;          // even
            size_t idx1 = (size_t)(row0 + 8) * 64 + nb * 8 + col0;    // even
            __half2 h0 = __floats2half2_rn(acc[g][nb][0], acc[g][nb][1]);
            __half2 h1 = __floats2half2_rn(acc[g][nb][2], acc[g][nb][3]);
            parth[idx0 >> 1] = *(unsigned*)&h0;
            parth[idx1 >> 1] = *(unsigned*)&h1;
        }
    }
}

// ---------------------------------------------------------------------------
// Reduce: out = sum(half2 partials, fixed order) + bias ; zero kl tail.
// Thread handles 8 output elems: 4 x uint4 (8 halves each) -> 2 x float4.
// ---------------------------------------------------------------------------
__global__ void wb_reduce(float* __restrict__ out, int out_size) {
    const int gid = blockIdx.x * blockDim.x + threadIdx.x;   // 0..OUT/8
    const uint4* p = (const uint4*)g_parth;                  // uint4 = 8 halves
    const int Q = OUT_ELEMS / 8;
    uint4 q0 = p[gid];
    uint4 q1 = p[gid + Q];
    uint4 q2 = p[gid + 2 * Q];
    uint4 q3 = p[gid + 3 * Q];

    const int c = (gid * 8) & 63;                // column of first elem
    const float4 bA = *(const float4*)&g_bias[c];
    const float4 bB = *(const float4*)&g_bias[c + 4];

#define H2F(u) __half22float2(*(__half2*)&(u))
    float2 s0, s1, s2, s3;
    s0 = H2F(q0.x); { float2 a = H2F(q1.x), b = H2F(q2.x), d = H2F(q3.x);
        s0.x = (s0.x + a.x) + (b.x + d.x); s0.y = (s0.y + a.y) + (b.y + d.y); }
    s1 = H2F(q0.y); { float2 a = H2F(q1.y), b = H2F(q2.y), d = H2F(q3.y);
        s1.x = (s1.x + a.x) + (b.x + d.x); s1.y = (s1.y + a.y) + (b.y + d.y); }
    s2 = H2F(q0.z); { float2 a = H2F(q1.z), b = H2F(q2.z), d = H2F(q3.z);
        s2.x = (s2.x + a.x) + (b.x + d.x); s2.y = (s2.y + a.y) + (b.y + d.y); }
    s3 = H2F(q0.w); { float2 a = H2F(q1.w), b = H2F(q2.w), d = H2F(q3.w);
        s3.x = (s3.x + a.x) + (b.x + d.x); s3.y = (s3.y + a.y) + (b.y + d.y); }
#undef H2F

    float4 rA, rB;
    rA.x = s0.x + bA.x;  rA.y = s0.y + bA.y;
    rA.z = s1.x + bA.z;  rA.w = s1.y + bA.w;
    rB.x = s2.x + bB.x;  rB.y = s2.y + bB.y;
    rB.z = s3.x + bB.z;  rB.w = s3.y + bB.w;
    ((float4*)out)[gid * 2]     = rA;
    ((float4*)out)[gid * 2 + 1] = rB;

    if (blockIdx.x == 0 && threadIdx.x == 0) {
        for (int k = OUT_ELEMS; k < out_size; k++) out[k] = 0.f;
    }
}

// ---------------------------------------------------------------------------
extern "C" void kernel_launch(void* const* d_in, const int* in_sizes, int n_in,
                              void* d_out, int out_size) {
    const float* x      = (const float*)d_in[0];   // [32768,1024] f32
    const float* coeffs = (const float*)d_in[1];   // [1024,64,8]  f32
    const float* bw     = (const float*)d_in[2];   // [1024,64]    f32
    float* out = (float*)d_out;

    wb_prep_B<<<512, 128>>>(coeffs, bw);
    wb_prep_bias<<<64, 128>>>(coeffs);
    wb_main<<<256 * NSPLIT, 128>>>(x);
    wb_reduce<<<OUT_ELEMS / 8 / 256, 256>>>(out, out_size);
}